// round 2
// baseline (speedup 1.0000x reference)
#include <cuda_runtime.h>
#include <cuda_bf16.h>

#define NMAX 8192
#define D 256
#define MARGIN 0.2f

// Scratch (allocation-free rule: __device__ globals)
__device__ float g_diag[NMAX];
__device__ int   g_rank1[NMAX];
__device__ int   g_rank2[NMAX];
__device__ int   g_rowcost[NMAX];   // float bits, values >= 0
__device__ int   g_colcost[NMAX];   // float bits, values >= 0

// ---------------------------------------------------------------------------
// Zero scratch + output (must run every call: graph replays reuse state)
// ---------------------------------------------------------------------------
__global__ void init_kernel(float* out, int n) {
    int i = blockIdx.x * blockDim.x + threadIdx.x;
    if (i < n) {
        g_rank1[i] = 0; g_rank2[i] = 0;
        g_rowcost[i] = 0; g_colcost[i] = 0;
    }
    if (i == 0) out[0] = 0.0f;
}

// ---------------------------------------------------------------------------
// diag_i = <im_i, s_i>, one warp per row
// ---------------------------------------------------------------------------
__global__ void diag_kernel(const float* __restrict__ im,
                            const float* __restrict__ s, int n) {
    int warp = (blockIdx.x * blockDim.x + threadIdx.x) >> 5;
    int lane = threadIdx.x & 31;
    if (warp >= n) return;
    const float4* a = (const float4*)(im + (size_t)warp * D);
    const float4* b = (const float4*)(s  + (size_t)warp * D);
    float acc = 0.0f;
#pragma unroll
    for (int k = lane; k < D / 4; k += 32) {
        float4 x = a[k], y = b[k];
        acc += x.x * y.x + x.y * y.y + x.z * y.z + x.w * y.w;
    }
#pragma unroll
    for (int o = 16; o > 0; o >>= 1) acc += __shfl_xor_sync(0xFFFFFFFFu, acc, o);
    if (lane == 0) g_diag[warp] = acc;
}

// ---------------------------------------------------------------------------
// Fused tile kernel: 128x128 score tile per block (SGEMM, K=256), epilogue
// folds tile into per-row / per-col rank counts and hinge maxima.
// 256 threads, each computes an 8x8 register tile.
// The diagonal element (i==j) is EXCLUDED from the rank count: in the
// reference the strict '<' against its own value is exactly false, and our
// separately-computed g_diag would otherwise spuriously count it.
// ---------------------------------------------------------------------------
#define BM 128
#define BN 128
#define BK 16

__global__ __launch_bounds__(256, 2)
void tile_kernel(const float* __restrict__ im, const float* __restrict__ s, int n) {
    __shared__ float As[BK][BM];
    __shared__ float Bs[BK][BN];
    __shared__ float diagR[BM];
    __shared__ float diagC[BN];
    __shared__ int   sRowCnt[BM];
    __shared__ int   sColCnt[BN];
    __shared__ int   sRowMax[BM];   // float bits (>=0)
    __shared__ int   sColMax[BN];

    const int i0 = blockIdx.y * BM;
    const int j0 = blockIdx.x * BN;
    const int tid = threadIdx.x;
    const int tx = tid & 15;        // 0..15 -> 8 cols each
    const int ty = tid >> 4;        // 0..15 -> 8 rows each

    if (tid < 128) {
        sRowCnt[tid] = 0; sColCnt[tid] = 0;
        sRowMax[tid] = 0; sColMax[tid] = 0;
        diagR[tid] = g_diag[i0 + tid];
        diagC[tid] = g_diag[j0 + tid];
    }

    float acc[8][8];
#pragma unroll
    for (int r = 0; r < 8; r++)
#pragma unroll
        for (int c = 0; c < 8; c++) acc[r][c] = 0.0f;

    for (int k0 = 0; k0 < D; k0 += BK) {
        __syncthreads();
        // Load A (im) and B (s) tiles, transposed into shared: As[k][row]
#pragma unroll
        for (int l = 0; l < 2; l++) {
            int id  = tid + l * 256;       // 0..511
            int row = id >> 2;             // 0..127
            int ch  = id & 3;              // float4 chunk within 16 cols
            float4 va = *(const float4*)(im + (size_t)(i0 + row) * D + k0 + ch * 4);
            As[ch * 4 + 0][row] = va.x;
            As[ch * 4 + 1][row] = va.y;
            As[ch * 4 + 2][row] = va.z;
            As[ch * 4 + 3][row] = va.w;
            float4 vb = *(const float4*)(s + (size_t)(j0 + row) * D + k0 + ch * 4);
            Bs[ch * 4 + 0][row] = vb.x;
            Bs[ch * 4 + 1][row] = vb.y;
            Bs[ch * 4 + 2][row] = vb.z;
            Bs[ch * 4 + 3][row] = vb.w;
        }
        __syncthreads();
#pragma unroll
        for (int kk = 0; kk < BK; kk++) {
            float a[8], b[8];
            *(float4*)&a[0] = *(const float4*)&As[kk][ty * 8];
            *(float4*)&a[4] = *(const float4*)&As[kk][ty * 8 + 4];
            *(float4*)&b[0] = *(const float4*)&Bs[kk][tx * 8];
            *(float4*)&b[4] = *(const float4*)&Bs[kk][tx * 8 + 4];
#pragma unroll
            for (int r = 0; r < 8; r++)
#pragma unroll
                for (int c = 0; c < 8; c++)
                    acc[r][c] = fmaf(a[r], b[c], acc[r][c]);
        }
    }

    // ---- epilogue: fold 8x8 tile into row / col statistics ----
    const int gi_base = i0 + ty * 8;
    const int gj_base = j0 + tx * 8;

#pragma unroll
    for (int r = 0; r < 8; r++) {
        float dr = diagR[ty * 8 + r];
        int   cnt = 0;
        float rmax = 0.0f;
#pragma unroll
        for (int c = 0; c < 8; c++) {
            float v = acc[r][c];
            bool offdiag = (gi_base + r != gj_base + c);
            cnt += (offdiag && (v < dr));
            if (offdiag)
                rmax = fmaxf(rmax, MARGIN + v - dr);
        }
        atomicAdd(&sRowCnt[ty * 8 + r], cnt);
        atomicMax(&sRowMax[ty * 8 + r], __float_as_int(rmax));
    }
#pragma unroll
    for (int c = 0; c < 8; c++) {
        float dc = diagC[tx * 8 + c];
        int   cnt = 0;
        float cmax = 0.0f;
#pragma unroll
        for (int r = 0; r < 8; r++) {
            float v = acc[r][c];
            bool offdiag = (gi_base + r != gj_base + c);
            cnt += (offdiag && (v < dc));
            if (offdiag)
                cmax = fmaxf(cmax, MARGIN + v - dc);
        }
        atomicAdd(&sColCnt[tx * 8 + c], cnt);
        atomicMax(&sColMax[tx * 8 + c], __float_as_int(cmax));
    }
    __syncthreads();

    if (tid < 128) {
        atomicAdd(&g_rank1[i0 + tid], sRowCnt[tid]);
        atomicMax(&g_rowcost[i0 + tid], sRowMax[tid]);
    } else {
        int t = tid - 128;
        atomicAdd(&g_rank2[j0 + t], sColCnt[t]);
        atomicMax(&g_colcost[j0 + t], sColMax[t]);
    }
}

// ---------------------------------------------------------------------------
// Deterministic single-block final reduction
// ---------------------------------------------------------------------------
__global__ void final_kernel(float* out, int n) {
    __shared__ float red[1024];
    float sum = 0.0f;
    for (int i = threadIdx.x; i < n; i += 1024) {
        float w1 = 1.0f / ((float)g_rank1[i] + 1.0f);
        float w2 = 1.0f / ((float)g_rank2[i] + 1.0f);
        sum += w1 * __int_as_float(g_rowcost[i]) + w2 * __int_as_float(g_colcost[i]);
    }
    red[threadIdx.x] = sum;
    __syncthreads();
#pragma unroll
    for (int sft = 512; sft > 0; sft >>= 1) {
        if (threadIdx.x < sft) red[threadIdx.x] += red[threadIdx.x + sft];
        __syncthreads();
    }
    if (threadIdx.x == 0) out[0] = red[0];
}

// ---------------------------------------------------------------------------
extern "C" void kernel_launch(void* const* d_in, const int* in_sizes, int n_in,
                              void* d_out, int out_size) {
    const float* im = (const float*)d_in[0];
    const float* s  = (const float*)d_in[1];
    float* out = (float*)d_out;
    const int n = in_sizes[0] / D;   // 8192

    init_kernel<<<(n + 255) / 256, 256>>>(out, n);
    diag_kernel<<<(n * 32 + 255) / 256, 256>>>(im, s, n);
    dim3 grid(n / BN, n / BM);
    tile_kernel<<<grid, 256>>>(im, s, n);
    final_kernel<<<1, 1024>>>(out, n);
}

// round 3
// speedup vs baseline: 1.0175x; 1.0175x over previous
#include <cuda_runtime.h>
#include <cuda_bf16.h>

#define NMAX 8192
#define D 256
#define MARGIN 0.2f

// Scratch (allocation-free rule: __device__ globals)
__device__ float g_diag[NMAX];
__device__ int   g_rank1[NMAX];
__device__ int   g_rank2[NMAX];
__device__ int   g_rowcost[NMAX];   // float bits, values >= 0
__device__ int   g_colcost[NMAX];   // float bits, values >= 0

// ---------------------------------------------------------------------------
// f32x2 packed helpers (FFMA2 — only reachable via PTX fma.rn.f32x2)
// ---------------------------------------------------------------------------
__device__ __forceinline__ unsigned long long fpack2(float x) {
    unsigned long long v;
    asm("mov.b64 %0, {%1, %1};" : "=l"(v) : "f"(x));
    return v;
}
__device__ __forceinline__ void ffma2(unsigned long long& d,
                                      unsigned long long a,
                                      unsigned long long b) {
    asm("fma.rn.f32x2 %0, %1, %2, %3;" : "=l"(d) : "l"(a), "l"(b), "l"(d));
}
__device__ __forceinline__ float2 unpk(unsigned long long v) {
    float2 f;
    asm("mov.b64 {%0, %1}, %2;" : "=f"(f.x), "=f"(f.y) : "l"(v));
    return f;
}

// ---------------------------------------------------------------------------
// Zero scratch + output (must run every call: graph replays reuse state)
// ---------------------------------------------------------------------------
__global__ void init_kernel(float* out, int n) {
    int i = blockIdx.x * blockDim.x + threadIdx.x;
    if (i < n) {
        g_rank1[i] = 0; g_rank2[i] = 0;
        g_rowcost[i] = 0; g_colcost[i] = 0;
    }
    if (i == 0) out[0] = 0.0f;
}

// ---------------------------------------------------------------------------
// diag_i = <im_i, s_i>, one warp per row
// ---------------------------------------------------------------------------
__global__ void diag_kernel(const float* __restrict__ im,
                            const float* __restrict__ s, int n) {
    int warp = (blockIdx.x * blockDim.x + threadIdx.x) >> 5;
    int lane = threadIdx.x & 31;
    if (warp >= n) return;
    const float4* a = (const float4*)(im + (size_t)warp * D);
    const float4* b = (const float4*)(s  + (size_t)warp * D);
    float acc = 0.0f;
#pragma unroll
    for (int k = lane; k < D / 4; k += 32) {
        float4 x = a[k], y = b[k];
        acc += x.x * y.x + x.y * y.y + x.z * y.z + x.w * y.w;
    }
#pragma unroll
    for (int o = 16; o > 0; o >>= 1) acc += __shfl_xor_sync(0xFFFFFFFFu, acc, o);
    if (lane == 0) g_diag[warp] = acc;
}

// ---------------------------------------------------------------------------
// Fused tile kernel: 256x128 score tile per block, FFMA2 (f32x2) math.
// 256 threads, each computes a 16x8 register tile as 8x8 f32x2 pairs
// (pairs along M). Epilogue folds the tile into per-row/per-col rank
// counts and hinge maxima. Diagonal (i==j) excluded from rank counts
// (strict '<' self-compare is exactly false in the reference).
// ---------------------------------------------------------------------------
#define BM 256
#define BN 128
#define BK 16

__global__ __launch_bounds__(256, 1)
void tile_kernel(const float* __restrict__ im, const float* __restrict__ s, int n) {
    __shared__ float As[BK][BM];      // transposed: As[k][row]
    __shared__ float Bs[BK][BN];
    __shared__ float diagR[BM];
    __shared__ float diagC[BN];
    __shared__ int   sRowCnt[BM];
    __shared__ int   sColCnt[BN];
    __shared__ int   sRowMax[BM];     // float bits (>=0)
    __shared__ int   sColMax[BN];

    const int i0 = blockIdx.y * BM;
    const int j0 = blockIdx.x * BN;
    const int tid = threadIdx.x;
    const int tx = tid & 15;          // 0..15 -> 8 cols each
    const int ty = tid >> 4;          // 0..15 -> 16 rows each

    sRowCnt[tid] = 0; sRowMax[tid] = 0;
    diagR[tid] = g_diag[i0 + tid];
    if (tid < BN) {
        sColCnt[tid] = 0; sColMax[tid] = 0;
        diagC[tid] = g_diag[j0 + tid];
    }

    unsigned long long acc[8][8];
#pragma unroll
    for (int mp = 0; mp < 8; mp++)
#pragma unroll
        for (int c = 0; c < 8; c++) acc[mp][c] = 0ull;

    for (int k0 = 0; k0 < D; k0 += BK) {
        __syncthreads();
        // A tile: each thread owns its row (tid), loads 4 float4 chunks.
        // Warp = 32 consecutive rows -> STS conflict-free. The half-sector
        // LDG waste is absorbed by L1 (same thread reads adjacent chunk).
#pragma unroll
        for (int l = 0; l < 4; l++) {
            float4 v = *(const float4*)(im + (size_t)(i0 + tid) * D + k0 + l * 4);
            As[l * 4 + 0][tid] = v.x;
            As[l * 4 + 1][tid] = v.y;
            As[l * 4 + 2][tid] = v.z;
            As[l * 4 + 3][tid] = v.w;
        }
        // B tile: 128 rows x 4 chunks = 512 tasks over 256 threads.
#pragma unroll
        for (int m = 0; m < 2; m++) {
            int ch  = m * 2 + (tid >> 7);
            int row = tid & 127;
            float4 v = *(const float4*)(s + (size_t)(j0 + row) * D + k0 + ch * 4);
            Bs[ch * 4 + 0][row] = v.x;
            Bs[ch * 4 + 1][row] = v.y;
            Bs[ch * 4 + 2][row] = v.z;
            Bs[ch * 4 + 3][row] = v.w;
        }
        __syncthreads();
#pragma unroll
        for (int kk = 0; kk < BK; kk++) {
            unsigned long long a2[8], b2[8];
#pragma unroll
            for (int mp = 0; mp < 8; mp++)
                a2[mp] = *(const unsigned long long*)&As[kk][ty * 16 + 2 * mp];
            float4 bv0 = *(const float4*)&Bs[kk][tx * 8];
            float4 bv1 = *(const float4*)&Bs[kk][tx * 8 + 4];
            b2[0] = fpack2(bv0.x); b2[1] = fpack2(bv0.y);
            b2[2] = fpack2(bv0.z); b2[3] = fpack2(bv0.w);
            b2[4] = fpack2(bv1.x); b2[5] = fpack2(bv1.y);
            b2[6] = fpack2(bv1.z); b2[7] = fpack2(bv1.w);
#pragma unroll
            for (int mp = 0; mp < 8; mp++)
#pragma unroll
                for (int c = 0; c < 8; c++)
                    ffma2(acc[mp][c], a2[mp], b2[c]);
        }
    }

    // ---- epilogue: fold 16x8 tile into row / col statistics ----
    const int gi_base = i0 + ty * 16;
    const int gj_base = j0 + tx * 8;

#pragma unroll
    for (int mp = 0; mp < 8; mp++) {
        float va[8], vb[8];
#pragma unroll
        for (int c = 0; c < 8; c++) {
            float2 t2 = unpk(acc[mp][c]);
            va[c] = t2.x; vb[c] = t2.y;
        }
#pragma unroll
        for (int h = 0; h < 2; h++) {
            const float* vv = h ? vb : va;
            int   lr = ty * 16 + 2 * mp + h;
            float dr = diagR[lr];
            int   cnt = 0;
            float rmax = 0.0f;
#pragma unroll
            for (int c = 0; c < 8; c++) {
                float v = vv[c];
                bool offd = (i0 + lr) != (gj_base + c);
                cnt += (offd && (v < dr));
                if (offd) rmax = fmaxf(rmax, MARGIN + v - dr);
            }
            atomicAdd(&sRowCnt[lr], cnt);
            atomicMax(&sRowMax[lr], __float_as_int(rmax));
        }
    }
#pragma unroll
    for (int c = 0; c < 8; c++) {
        float dc = diagC[tx * 8 + c];
        int   cnt = 0;
        float cmax = 0.0f;
#pragma unroll
        for (int mp = 0; mp < 8; mp++) {
            float2 t2 = unpk(acc[mp][c]);
            int  r0 = gi_base + 2 * mp;
            bool od0 = (r0     != gj_base + c);
            bool od1 = (r0 + 1 != gj_base + c);
            cnt += (od0 && (t2.x < dc));
            cnt += (od1 && (t2.y < dc));
            if (od0) cmax = fmaxf(cmax, MARGIN + t2.x - dc);
            if (od1) cmax = fmaxf(cmax, MARGIN + t2.y - dc);
        }
        atomicAdd(&sColCnt[tx * 8 + c], cnt);
        atomicMax(&sColMax[tx * 8 + c], __float_as_int(cmax));
    }
    __syncthreads();

    atomicAdd(&g_rank1[i0 + tid], sRowCnt[tid]);
    atomicMax(&g_rowcost[i0 + tid], sRowMax[tid]);
    if (tid < BN) {
        atomicAdd(&g_rank2[j0 + tid], sColCnt[tid]);
        atomicMax(&g_colcost[j0 + tid], sColMax[tid]);
    }
}

// ---------------------------------------------------------------------------
// Deterministic single-block final reduction (vectorized, shuffle tree)
// ---------------------------------------------------------------------------
__global__ void final_kernel(float* out, int n) {
    __shared__ float red[32];
    const int t = threadIdx.x;                  // 1024 threads
    const int nv = n / 4;                       // int4 count per array
    float sum = 0.0f;
#pragma unroll
    for (int v = 0; v < 2; v++) {
        int i = t + v * 1024;
        if (i < nv) {
            int4 r1 = ((const int4*)g_rank1)[i];
            int4 r2 = ((const int4*)g_rank2)[i];
            int4 rc = ((const int4*)g_rowcost)[i];
            int4 cc = ((const int4*)g_colcost)[i];
            sum += __int_as_float(rc.x) / ((float)r1.x + 1.0f)
                 + __int_as_float(rc.y) / ((float)r1.y + 1.0f)
                 + __int_as_float(rc.z) / ((float)r1.z + 1.0f)
                 + __int_as_float(rc.w) / ((float)r1.w + 1.0f)
                 + __int_as_float(cc.x) / ((float)r2.x + 1.0f)
                 + __int_as_float(cc.y) / ((float)r2.y + 1.0f)
                 + __int_as_float(cc.z) / ((float)r2.z + 1.0f)
                 + __int_as_float(cc.w) / ((float)r2.w + 1.0f);
        }
    }
#pragma unroll
    for (int o = 16; o > 0; o >>= 1) sum += __shfl_xor_sync(0xFFFFFFFFu, sum, o);
    if ((t & 31) == 0) red[t >> 5] = sum;
    __syncthreads();
    if (t < 32) {
        float v = red[t];
#pragma unroll
        for (int o = 16; o > 0; o >>= 1) v += __shfl_xor_sync(0xFFFFFFFFu, v, o);
        if (t == 0) out[0] = v;
    }
}

// ---------------------------------------------------------------------------
extern "C" void kernel_launch(void* const* d_in, const int* in_sizes, int n_in,
                              void* d_out, int out_size) {
    const float* im = (const float*)d_in[0];
    const float* s  = (const float*)d_in[1];
    float* out = (float*)d_out;
    const int n = in_sizes[0] / D;   // 8192

    init_kernel<<<(n + 255) / 256, 256>>>(out, n);
    diag_kernel<<<(n * 32 + 255) / 256, 256>>>(im, s, n);
    dim3 grid(n / BN, n / BM);
    tile_kernel<<<grid, 256>>>(im, s, n);
    final_kernel<<<1, 1024>>>(out, n);
}

// round 5
// speedup vs baseline: 1.2259x; 1.2048x over previous
#include <cuda_runtime.h>
#include <cuda_bf16.h>
#include <cstdint>

#define NMAX 8192
#define D 256
#define KP 768                 // 3x-split K: A'=[hi|lo|hi], B'=[hi|hi|lo]
#define MARGIN 0.2f
#define FULLW 0xFFFFFFFFu

// ---------------------------------------------------------------------------
// Scratch (allocation-free rule: __device__ globals)
// ---------------------------------------------------------------------------
__device__ float g_diag[NMAX];
__device__ int   g_rank1[NMAX];
__device__ int   g_rank2[NMAX];
__device__ int   g_rowcost[NMAX];   // float bits, values >= 0
__device__ int   g_colcost[NMAX];   // float bits, values >= 0
__device__ float g_A[NMAX * KP];    // 24 MB
__device__ float g_B[NMAX * KP];    // 24 MB

// ---------------------------------------------------------------------------
// helpers
// ---------------------------------------------------------------------------
__device__ __forceinline__ uint32_t smem_u32(const void* p) {
    uint32_t a;
    asm("{ .reg .u64 t; cvta.to.shared.u64 t, %1; cvt.u32.u64 %0, t; }"
        : "=r"(a) : "l"(p));
    return a;
}
__device__ __forceinline__ float tf32r(float x) {
    uint32_t u;
    asm("cvt.rna.tf32.f32 %0, %1;" : "=r"(u) : "f"(x));
    return __uint_as_float(u);
}
__device__ __forceinline__ void cp16(uint32_t dst, const void* src) {
    asm volatile("cp.async.cg.shared.global [%0], [%1], 16;"
                 :: "r"(dst), "l"(src));
}
__device__ __forceinline__ void mma_tf32(float* d, const uint32_t* a, const uint32_t* b) {
    asm volatile(
        "mma.sync.aligned.m16n8k8.row.col.f32.tf32.tf32.f32 "
        "{%0,%1,%2,%3}, {%4,%5,%6,%7}, {%8,%9}, {%0,%1,%2,%3};"
        : "+f"(d[0]), "+f"(d[1]), "+f"(d[2]), "+f"(d[3])
        : "r"(a[0]), "r"(a[1]), "r"(a[2]), "r"(a[3]), "r"(b[0]), "r"(b[1]));
}

// ---------------------------------------------------------------------------
// init: zero scratch + output
// ---------------------------------------------------------------------------
__global__ void init_kernel(float* out, int n) {
    int i = blockIdx.x * blockDim.x + threadIdx.x;
    if (i < n) {
        g_rank1[i] = 0; g_rank2[i] = 0;
        g_rowcost[i] = 0; g_colcost[i] = 0;
    }
    if (i == 0) out[0] = 0.0f;
}

// ---------------------------------------------------------------------------
// split: A' = [hi|lo|hi], B' = [hi|hi|lo] (tf32-rounded split of fp32)
// ---------------------------------------------------------------------------
__global__ void split_kernel(const float* __restrict__ im, const float* __restrict__ s) {
    int g = blockIdx.x * blockDim.x + threadIdx.x;   // 0 .. 8192*64-1
    int row = g >> 6, c4 = g & 63;
    size_t src = (size_t)row * D + c4 * 4;
    size_t dst = (size_t)row * KP + c4 * 4;

    float4 a = *(const float4*)(im + src);
    float4 ah, al;
    ah.x = tf32r(a.x); al.x = tf32r(a.x - ah.x);
    ah.y = tf32r(a.y); al.y = tf32r(a.y - ah.y);
    ah.z = tf32r(a.z); al.z = tf32r(a.z - ah.z);
    ah.w = tf32r(a.w); al.w = tf32r(a.w - ah.w);
    *(float4*)(g_A + dst)       = ah;
    *(float4*)(g_A + dst + 256) = al;
    *(float4*)(g_A + dst + 512) = ah;

    float4 b = *(const float4*)(s + src);
    float4 bh, bl;
    bh.x = tf32r(b.x); bl.x = tf32r(b.x - bh.x);
    bh.y = tf32r(b.y); bl.y = tf32r(b.y - bh.y);
    bh.z = tf32r(b.z); bl.z = tf32r(b.z - bh.z);
    bh.w = tf32r(b.w); bl.w = tf32r(b.w - bh.w);
    *(float4*)(g_B + dst)       = bh;
    *(float4*)(g_B + dst + 256) = bh;
    *(float4*)(g_B + dst + 512) = bl;
}

// ---------------------------------------------------------------------------
// diag_i = <im_i, s_i> in fp32, one warp per row
// ---------------------------------------------------------------------------
__global__ void diag_kernel(const float* __restrict__ im,
                            const float* __restrict__ s, int n) {
    int warp = (blockIdx.x * blockDim.x + threadIdx.x) >> 5;
    int lane = threadIdx.x & 31;
    if (warp >= n) return;
    const float4* a = (const float4*)(im + (size_t)warp * D);
    const float4* b = (const float4*)(s  + (size_t)warp * D);
    float acc = 0.0f;
#pragma unroll
    for (int k = lane; k < D / 4; k += 32) {
        float4 x = a[k], y = b[k];
        acc += x.x * y.x + x.y * y.y + x.z * y.z + x.w * y.w;
    }
#pragma unroll
    for (int o = 16; o > 0; o >>= 1) acc += __shfl_xor_sync(FULLW, acc, o);
    if (lane == 0) g_diag[warp] = acc;
}

// ---------------------------------------------------------------------------
// Fused mma.sync tf32 tile kernel: 256x128 score tile per CTA.
// 8 warps (2 N x 4 M), warp tile 64x64, m16n8k8, K=768, BK=32, 2 stages.
// Smem layout: row-major [row][k] padded to 36 words/row (conflict-free
// fragment LDS and staging STS).
// ---------------------------------------------------------------------------
#define BM 256
#define BN 128
#define BK 32
#define ROWPAD 36
#define NSTAGE (KP / BK)        // 24
#define AS_WORDS (BM * ROWPAD)  // 9216 per stage
#define BS_WORDS (BN * ROWPAD)  // 4608 per stage
#define AS_OFF 0
#define BS_OFF (2 * AS_WORDS)                 // 18432
#define DIAGR_OFF (BS_OFF + 2 * BS_WORDS)     // 27648
#define DIAGC_OFF (DIAGR_OFF + 256)           // 27904
#define RCNT_OFF  (DIAGC_OFF + 128)           // 28032
#define RMAX_OFF  (RCNT_OFF + 256)            // 28288
#define CCNT_OFF  (RMAX_OFF + 256)            // 28544
#define CMAX_OFF  (CCNT_OFF + 128)            // 28672
#define SMEM_WORDS (CMAX_OFF + 128)           // 28800
#define SMEM_BYTES (SMEM_WORDS * 4)           // 115200

__global__ __launch_bounds__(256, 1)
void tile_kernel() {
    extern __shared__ __align__(16) float smem[];
    uint32_t* smu = (uint32_t*)smem;
    int* sRCnt = (int*)(smem + RCNT_OFF);
    int* sRMax = (int*)(smem + RMAX_OFF);
    int* sCCnt = (int*)(smem + CCNT_OFF);
    int* sCMax = (int*)(smem + CMAX_OFF);

    const int tid  = threadIdx.x;
    const int wid  = tid >> 5;
    const int lane = tid & 31;
    const int wm   = wid >> 1;          // 0..3  -> M offset wm*64
    const int wn   = wid & 1;           // 0..1  -> N offset wn*64
    const int grp  = lane >> 2;         // 0..7
    const int tig  = lane & 3;          // 0..3
    const int i0 = blockIdx.y * BM;
    const int j0 = blockIdx.x * BN;
    const uint32_t sb = smem_u32(smem);

    // stats init + diag preload
    smem[DIAGR_OFF + tid] = g_diag[i0 + tid];
    sRCnt[tid] = 0; sRMax[tid] = 0;
    if (tid < 128) {
        smem[DIAGC_OFF + tid] = g_diag[j0 + tid];
        sCCnt[tid] = 0; sCMax[tid] = 0;
    }
    __syncthreads();

    float acc[4][8][4];
#pragma unroll
    for (int mt = 0; mt < 4; mt++)
#pragma unroll
        for (int nt = 0; nt < 8; nt++)
#pragma unroll
            for (int e = 0; e < 4; e++) acc[mt][nt][e] = 0.0f;

    // precomputed per-thread staging indices
    const int ldrow = tid >> 3;         // 0..31 base row
    const int ldch  = tid & 7;          // chunk (4 floats)
    const float* Abase = g_A + (size_t)(i0 + ldrow) * KP + ldch * 4;
    const float* Bbase = g_B + (size_t)(j0 + ldrow) * KP + ldch * 4;

    // ---- prologue: stage 0 ----
    {
        uint32_t adst = sb + (AS_OFF + ldrow * ROWPAD + ldch * 4) * 4;
        uint32_t bdst = sb + (BS_OFF + ldrow * ROWPAD + ldch * 4) * 4;
#pragma unroll
        for (int q = 0; q < 8; q++)
            cp16(adst + q * 32 * ROWPAD * 4, Abase + (size_t)(q * 32) * KP);
#pragma unroll
        for (int q = 0; q < 4; q++)
            cp16(bdst + q * 32 * ROWPAD * 4, Bbase + (size_t)(q * 32) * KP);
        asm volatile("cp.async.commit_group;");
    }

    for (int st = 0; st < NSTAGE; st++) {
        const int cur = st & 1;
        if (st + 1 < NSTAGE) {
            const int nxt = (st + 1) & 1;
            uint32_t adst = sb + (AS_OFF + nxt * AS_WORDS + ldrow * ROWPAD + ldch * 4) * 4;
            uint32_t bdst = sb + (BS_OFF + nxt * BS_WORDS + ldrow * ROWPAD + ldch * 4) * 4;
            const float* as = Abase + (st + 1) * BK;
            const float* bs = Bbase + (st + 1) * BK;
#pragma unroll
            for (int q = 0; q < 8; q++)
                cp16(adst + q * 32 * ROWPAD * 4, as + (size_t)(q * 32) * KP);
#pragma unroll
            for (int q = 0; q < 4; q++)
                cp16(bdst + q * 32 * ROWPAD * 4, bs + (size_t)(q * 32) * KP);
            asm volatile("cp.async.commit_group;");
            asm volatile("cp.async.wait_group 1;");
        } else {
            asm volatile("cp.async.wait_group 0;");
        }
        __syncthreads();

        const uint32_t* As = smu + AS_OFF + cur * AS_WORDS;
        const uint32_t* Bs = smu + BS_OFF + cur * BS_WORDS;
#pragma unroll
        for (int k8 = 0; k8 < BK / 8; k8++) {
            uint32_t afr[4][4];
#pragma unroll
            for (int mt = 0; mt < 4; mt++) {
                const uint32_t* ap = As + (wm * 64 + mt * 16 + grp) * ROWPAD + k8 * 8 + tig;
                afr[mt][0] = ap[0];
                afr[mt][1] = ap[8 * ROWPAD];
                afr[mt][2] = ap[4];
                afr[mt][3] = ap[8 * ROWPAD + 4];
            }
#pragma unroll
            for (int nt = 0; nt < 8; nt++) {
                const uint32_t* bp = Bs + (wn * 64 + nt * 8 + grp) * ROWPAD + k8 * 8 + tig;
                uint32_t bfr[2];
                bfr[0] = bp[0];
                bfr[1] = bp[4];
#pragma unroll
                for (int mt = 0; mt < 4; mt++)
                    mma_tf32(acc[mt][nt], afr[mt], bfr);
            }
        }
        __syncthreads();
    }

    // ---- epilogue ----
    // Row stats: thread's rows = i0 + wm*64 + mt*16 + grp + h*8
#pragma unroll
    for (int mt = 0; mt < 4; mt++) {
#pragma unroll
        for (int h = 0; h < 2; h++) {
            const int rin = wm * 64 + mt * 16 + grp + h * 8;
            const int gi = i0 + rin;
            const float dr = smem[DIAGR_OFF + rin];
            int cnt = 0;
            float rmax = 0.0f;
#pragma unroll
            for (int nt = 0; nt < 8; nt++) {
#pragma unroll
                for (int e = 0; e < 2; e++) {
                    const int cin = wn * 64 + nt * 8 + 2 * tig + e;
                    float v = acc[mt][nt][h * 2 + e];
                    bool od = (gi != j0 + cin);
                    cnt += (od && (v < dr));
                    if (od) rmax = fmaxf(rmax, (MARGIN + v) - dr);
                }
            }
            // reduce over tig (xor 1,2) — rows identical across those lanes
            cnt  += __shfl_xor_sync(FULLW, cnt, 1);
            rmax  = fmaxf(rmax, __shfl_xor_sync(FULLW, rmax, 1));
            cnt  += __shfl_xor_sync(FULLW, cnt, 2);
            rmax  = fmaxf(rmax, __shfl_xor_sync(FULLW, rmax, 2));
            if (tig == 0) {
                atomicAdd(&sRCnt[rin], cnt);
                atomicMax(&sRMax[rin], __float_as_int(rmax));
            }
        }
    }
    // Col stats: thread's cols = j0 + wn*64 + nt*8 + 2*tig + e
#pragma unroll
    for (int nt = 0; nt < 8; nt++) {
#pragma unroll
        for (int e = 0; e < 2; e++) {
            const int cin = wn * 64 + nt * 8 + 2 * tig + e;
            const float dc = smem[DIAGC_OFF + cin];
            int cnt = 0;
            float cmax = 0.0f;
#pragma unroll
            for (int mt = 0; mt < 4; mt++) {
#pragma unroll
                for (int h = 0; h < 2; h++) {
                    const int gi = i0 + wm * 64 + mt * 16 + grp + h * 8;
                    float v = acc[mt][nt][h * 2 + e];
                    bool od = (gi != j0 + cin);
                    cnt += (od && (v < dc));
                    if (od) cmax = fmaxf(cmax, (MARGIN + v) - dc);
                }
            }
            // reduce over grp (xor 4,8,16) — cols identical across those lanes
            cnt  += __shfl_xor_sync(FULLW, cnt, 4);
            cmax  = fmaxf(cmax, __shfl_xor_sync(FULLW, cmax, 4));
            cnt  += __shfl_xor_sync(FULLW, cnt, 8);
            cmax  = fmaxf(cmax, __shfl_xor_sync(FULLW, cmax, 8));
            cnt  += __shfl_xor_sync(FULLW, cnt, 16);
            cmax  = fmaxf(cmax, __shfl_xor_sync(FULLW, cmax, 16));
            if (grp == 0) {
                atomicAdd(&sCCnt[cin], cnt);
                atomicMax(&sCMax[cin], __float_as_int(cmax));
            }
        }
    }
    __syncthreads();

    atomicAdd(&g_rank1[i0 + tid], sRCnt[tid]);
    atomicMax(&g_rowcost[i0 + tid], sRMax[tid]);
    if (tid < 128) {
        atomicAdd(&g_rank2[j0 + tid], sCCnt[tid]);
        atomicMax(&g_colcost[j0 + tid], sCMax[tid]);
    }
}

// ---------------------------------------------------------------------------
// Deterministic final reduction
// ---------------------------------------------------------------------------
__global__ void final_kernel(float* out, int n) {
    __shared__ float red[32];
    const int t = threadIdx.x;
    const int nv = n / 4;
    float sum = 0.0f;
#pragma unroll
    for (int v = 0; v < 2; v++) {
        int i = t + v * 1024;
        if (i < nv) {
            int4 r1 = ((const int4*)g_rank1)[i];
            int4 r2 = ((const int4*)g_rank2)[i];
            int4 rc = ((const int4*)g_rowcost)[i];
            int4 cc = ((const int4*)g_colcost)[i];
            sum += __int_as_float(rc.x) / ((float)r1.x + 1.0f)
                 + __int_as_float(rc.y) / ((float)r1.y + 1.0f)
                 + __int_as_float(rc.z) / ((float)r1.z + 1.0f)
                 + __int_as_float(rc.w) / ((float)r1.w + 1.0f)
                 + __int_as_float(cc.x) / ((float)r2.x + 1.0f)
                 + __int_as_float(cc.y) / ((float)r2.y + 1.0f)
                 + __int_as_float(cc.z) / ((float)r2.z + 1.0f)
                 + __int_as_float(cc.w) / ((float)r2.w + 1.0f);
        }
    }
#pragma unroll
    for (int o = 16; o > 0; o >>= 1) sum += __shfl_xor_sync(FULLW, sum, o);
    if ((t & 31) == 0) red[t >> 5] = sum;
    __syncthreads();
    if (t < 32) {
        float v = red[t];
#pragma unroll
        for (int o = 16; o > 0; o >>= 1) v += __shfl_xor_sync(FULLW, v, o);
        if (t == 0) out[0] = v;
    }
}

// ---------------------------------------------------------------------------
extern "C" void kernel_launch(void* const* d_in, const int* in_sizes, int n_in,
                              void* d_out, int out_size) {
    const float* im = (const float*)d_in[0];
    const float* s  = (const float*)d_in[1];
    float* out = (float*)d_out;
    const int n = in_sizes[0] / D;   // 8192

    cudaFuncSetAttribute(tile_kernel,
                         cudaFuncAttributeMaxDynamicSharedMemorySize, SMEM_BYTES);

    init_kernel<<<(n + 255) / 256, 256>>>(out, n);
    split_kernel<<<(n * (D / 4) + 255) / 256, 256>>>(im, s);
    diag_kernel<<<(n * 32 + 255) / 256, 256>>>(im, s, n);
    dim3 grid(n / BN, n / BM);
    tile_kernel<<<grid, 256, SMEM_BYTES>>>();
    final_kernel<<<1, 1024>>>(out, n);
}